// round 14
// baseline (speedup 1.0000x reference)
#include <cuda_runtime.h>
#include <cuda_bf16.h>
#include <cstdint>

// Problem constants (fixed by setup_inputs)
#define KC   8
#define DIM  512
#define HID  512
#define AC   1024
#define SQ   64
#define TT   128
#define BB   8192

// ---------------- device scratch --------------------------------------------
__device__ float         g_obs_tf[BB * DIM];                  //  16 MB (tf32)
__device__ float         g_W1_tf[KC * DIM * HID];             //  16 MB (tf32)
__device__ float         g_h[(size_t)KC * BB * HID];          // 128 MB fp32
__device__ __nv_bfloat16 g_h_bf[(size_t)KC * BB * HID];       //  64 MB
__device__ __nv_bfloat16 g_W2t_bf[KC * AC * HID];             //   8 MB [k][a][h]
__device__ float         g_W2t_f[KC * AC * HID];              //  16 MB [k][a][h]
__device__ __nv_bfloat16 g_logits_bf[(size_t)KC * BB * AC];   // 128 MB
__device__ float         g_pmax[KC * 32 * BB];                //   8 MB
__device__ float         g_psum[KC * 32 * BB];                //   8 MB
__device__ float         g_lse[KC * BB];
__device__ float         g_alp[KC * BB];
__device__ float         g_mix[KC * BB];
__device__ int           g_act[BB];

__device__ __forceinline__ float f2tf32(float x) {
    float r;
    asm("cvt.rna.tf32.f32 %0, %1;" : "=f"(r) : "f"(x));
    return r;
}

// ---------------- obs/W1 fp32 -> tf32 ---------------------------------------
__global__ void convert_kernel(const float* __restrict__ obs,
                               const float* __restrict__ W1) {
    int i = blockIdx.x * blockDim.x + threadIdx.x;
    const int n_obs = BB * DIM;
    const int n_w1  = KC * DIM * HID;
    if (i < n_obs) { g_obs_tf[i] = f2tf32(obs[i]); return; }
    int j = i - n_obs;
    if (j < n_w1)  { g_W1_tf[j] = f2tf32(W1[j]); }
}

// W2 [k][512 d][1024 a] -> [k][a][d] as bf16 AND fp32. block (32,8), grid (32,16,8)
__global__ void transpose_w2_kernel(const float* __restrict__ W2) {
    __shared__ float t[32][33];
    const int k = blockIdx.z;
    const int c0 = blockIdx.x * 32, r0 = blockIdx.y * 32;   // c over A, r over D
    const float* src = W2 + (size_t)k * DIM * AC;
    const int x = threadIdx.x, y = threadIdx.y;
#pragma unroll
    for (int i = 0; i < 32; i += 8)
        t[y + i][x] = src[(size_t)(r0 + y + i) * AC + c0 + x];
    __syncthreads();
#pragma unroll
    for (int i = 0; i < 32; i += 8) {
        const float v = t[x][y + i];
        const size_t o = (size_t)k * AC * HID + (size_t)(c0 + y + i) * HID + r0 + x;
        g_W2t_f[o]  = v;
        g_W2t_bf[o] = __float2bfloat16(v);
    }
}

// ---------------- actions: detect int32 vs int64, normalize to int32 --------
__global__ void prep_actions_kernel(const void* __restrict__ act) {
    const unsigned long long* p64 = (const unsigned long long*)act;
    int bad = 0;
    for (int i = threadIdx.x; i < BB / 2; i += blockDim.x)
        if (p64[i] > 0xFFFFFFFFull) bad = 1;
    int is32 = __syncthreads_or(bad);
    if (is32) {
        const int* p32 = (const int*)act;
        for (int i = threadIdx.x; i < BB; i += blockDim.x) g_act[i] = p32[i];
    } else {
        const long long* pl = (const long long*)act;
        for (int i = threadIdx.x; i < BB; i += blockDim.x) g_act[i] = (int)pl[i];
    }
}

// ---------------- mma helpers -----------------------------------------------
__device__ __forceinline__ void mma1688(float* c, const unsigned* a, const unsigned* b) {
    asm volatile(
        "mma.sync.aligned.m16n8k8.row.col.f32.tf32.tf32.f32 "
        "{%0,%1,%2,%3}, {%4,%5,%6,%7}, {%8,%9}, {%0,%1,%2,%3};\n"
        : "+f"(c[0]), "+f"(c[1]), "+f"(c[2]), "+f"(c[3])
        : "r"(a[0]), "r"(a[1]), "r"(a[2]), "r"(a[3]), "r"(b[0]), "r"(b[1]));
}
__device__ __forceinline__ void mma16816bf(float* c, const unsigned* a, const unsigned* b) {
    asm volatile(
        "mma.sync.aligned.m16n8k16.row.col.f32.bf16.bf16.f32 "
        "{%0,%1,%2,%3}, {%4,%5,%6,%7}, {%8,%9}, {%0,%1,%2,%3};\n"
        : "+f"(c[0]), "+f"(c[1]), "+f"(c[2]), "+f"(c[3])
        : "r"(a[0]), "r"(a[1]), "r"(a[2]), "r"(a[3]), "r"(b[0]), "r"(b[1]));
}

#define LDSM_X4(r0, r1, r2, r3, addr) \
    asm volatile("ldmatrix.sync.aligned.m8n8.x4.shared.b16 {%0,%1,%2,%3}, [%4];" \
                 : "=r"(r0), "=r"(r1), "=r"(r2), "=r"(r3) : "r"(addr))

#define CPASYNC16(dst, src) \
    asm volatile("cp.async.ca.shared.global [%0], [%1], 16;" :: "r"(dst), "l"(src))
#define CP_COMMIT() asm volatile("cp.async.commit_group;" ::: "memory")

// ============================================================================
// GEMM1 (tf32): h = relu(obs @ W1 + b1). 512 thr, 16 warps 4m x 4n, warp 32x32.
// ============================================================================
#define NSTAGE     3
#define KSTEPS     16
#define A_TILE_B   16384
#define B_STRIDE   136
#define B_TILE_F   (32 * B_STRIDE)
#define B_BASE_B   (NSTAGE * A_TILE_B)
#define SMEM1_BYTES (B_BASE_B + NSTAGE * B_TILE_F * 4)   // 101376

__device__ __forceinline__ void g1_load(int s, int tid, uint32_t smem_u32,
                                        const float* Ag, const float* Bg,
                                        int base_m, int base_n) {
    const int buf = s % NSTAGE;
    const uint32_t abase = smem_u32 + buf * A_TILE_B;
    const uint32_t bbase = smem_u32 + B_BASE_B + buf * (B_TILE_F * 4);
    const int kofs = s * 32;
#pragma unroll
    for (int i = 0; i < 2; i++) {
        const int idx = tid + 512 * i;                 // 0..1023
        const int row = idx >> 3, kc = idx & 7;
        const uint32_t doff = (uint32_t)(row * 128 + ((kc * 16) ^ ((row & 7) << 4)));
        CPASYNC16(abase + doff, Ag + (size_t)(base_m + row) * 512 + kofs + kc * 4);
        const int kr = idx >> 5, nq = (idx & 31) * 4;
        CPASYNC16(bbase + (uint32_t)((kr * B_STRIDE + nq) * 4),
                  Bg + (size_t)(kofs + kr) * HID + base_n + nq);
    }
    CP_COMMIT();
}

__global__ void __launch_bounds__(512, 2) gemm1_tc(const float* __restrict__ bias_all) {
    extern __shared__ float sm[];
    const uint32_t smem_u32 = (uint32_t)__cvta_generic_to_shared(sm);
    const int tid = threadIdx.x, wid = tid >> 5, lane = tid & 31;
    const int kcomp = blockIdx.z, bm = blockIdx.y, bn = blockIdx.x;
    const int base_m = bm * 128, base_n = bn * 128;
    const int wm = (wid >> 2) * 32, wn = (wid & 3) * 32;

    const float* Ag = g_obs_tf;
    const float* Bg = g_W1_tf + (size_t)kcomp * DIM * HID;

    float acc[2][4][4];
#pragma unroll
    for (int i = 0; i < 2; i++)
#pragma unroll
        for (int j = 0; j < 4; j++)
#pragma unroll
            for (int l = 0; l < 4; l++) acc[i][j][l] = 0.f;

    const int a_hi = (lane >> 4) & 1;
    const int a_r8 = (lane >> 3) & 1;
    uint32_t a_base[2];
#pragma unroll
    for (int mf = 0; mf < 2; mf++) {
        const int row = wm + mf * 16 + a_r8 * 8 + (lane & 7);
        a_base[mf] = (uint32_t)(row * 128 + ((a_hi * 16) ^ ((row & 7) << 4)));
    }

    g1_load(0, tid, smem_u32, Ag, Bg, base_m, base_n);
    g1_load(1, tid, smem_u32, Ag, Bg, base_m, base_n);

    for (int s = 0; s < KSTEPS; s++) {
        if (s + 2 < KSTEPS) {
            g1_load(s + 2, tid, smem_u32, Ag, Bg, base_m, base_n);
            asm volatile("cp.async.wait_group 2;" ::: "memory");
        } else if (s + 1 < KSTEPS) {
            asm volatile("cp.async.wait_group 1;" ::: "memory");
        } else {
            asm volatile("cp.async.wait_group 0;" ::: "memory");
        }
        __syncthreads();

        const uint32_t As = smem_u32 + (s % NSTAGE) * A_TILE_B;
        const float* Bs = sm + (B_BASE_B / 4) + (s % NSTAGE) * B_TILE_F;

#pragma unroll
        for (int k8 = 0; k8 < 4; k8++) {
            const uint32_t kx = (uint32_t)(k8 * 32);
            const int kb = k8 * 8;
            unsigned a[2][4], b[4][2];
#pragma unroll
            for (int mf = 0; mf < 2; mf++)
                LDSM_X4(a[mf][0], a[mf][1], a[mf][2], a[mf][3], As + (a_base[mf] ^ kx));
#pragma unroll
            for (int nf = 0; nf < 4; nf++) {
                const int col = wn + nf * 8 + (lane >> 2);
                const int r0 = kb + (lane & 3);
                b[nf][0] = __float_as_uint(Bs[r0 * B_STRIDE + col]);
                b[nf][1] = __float_as_uint(Bs[(r0 + 4) * B_STRIDE + col]);
            }
#pragma unroll
            for (int mf = 0; mf < 2; mf++)
#pragma unroll
                for (int nf = 0; nf < 4; nf++) mma1688(acc[mf][nf], a[mf], b[nf]);
        }
        __syncthreads();
    }

    // epilogue: h fp32 + h bf16
    const float* bias = bias_all + (size_t)kcomp * HID;
    const int q = lane >> 2;
    float* outp = g_h + (size_t)kcomp * BB * HID;
    __nv_bfloat16* outb = g_h_bf + (size_t)kcomp * BB * HID;
#pragma unroll
    for (int mf = 0; mf < 2; mf++) {
        const int row = base_m + wm + mf * 16 + q;
#pragma unroll
        for (int nf = 0; nf < 4; nf++) {
            const int col = base_n + wn + nf * 8 + (lane & 3) * 2;
            const float bv0 = bias[col], bv1 = bias[col + 1];
            float v0 = fmaxf(acc[mf][nf][0] + bv0, 0.f);
            float v1 = fmaxf(acc[mf][nf][1] + bv1, 0.f);
            float v2 = fmaxf(acc[mf][nf][2] + bv0, 0.f);
            float v3 = fmaxf(acc[mf][nf][3] + bv1, 0.f);
            *(float2*)(outp + (size_t)row * HID + col) = make_float2(v0, v1);
            *(float2*)(outp + (size_t)(row + 8) * HID + col) = make_float2(v2, v3);
            __nv_bfloat162 q0, q1;
            q0.x = __float2bfloat16(v0); q0.y = __float2bfloat16(v1);
            q1.x = __float2bfloat16(v2); q1.y = __float2bfloat16(v3);
            *(__nv_bfloat162*)(outb + (size_t)row * HID + col) = q0;
            *(__nv_bfloat162*)(outb + (size_t)(row + 8) * HID + col) = q1;
        }
    }
}

// ============================================================================
// GEMM2 (bf16 m16n8k16): logits = h_bf @ W2t_bf^T + b2, fused partial-LSE
// 512 thr, 16 warps 4m x 4n, warp 32x32. Logits stored bf16.
// ============================================================================
#define G2_NSTAGE  3
#define G2_KSTEPS  8                            // 512 / 64
#define G2_TILE_B  16384
#define G2_STAGE_B (2 * G2_TILE_B)
#define SMEM2_BYTES (G2_NSTAGE * G2_STAGE_B)    // 98304

__device__ __forceinline__ void g2_load(int s, int tid, uint32_t smem_u32,
                                        const __nv_bfloat16* Ag, const __nv_bfloat16* Bt,
                                        int base_m, int base_n) {
    const uint32_t abase = smem_u32 + (s % G2_NSTAGE) * G2_STAGE_B;
    const uint32_t bbase = abase + G2_TILE_B;
    const int kofs = s * 64;
#pragma unroll
    for (int i = 0; i < 2; i++) {
        const int idx = tid + 512 * i;
        const int row = idx >> 3, kc = idx & 7;
        const uint32_t doff = (uint32_t)(row * 128 + ((kc * 16) ^ ((row & 7) << 4)));
        CPASYNC16(abase + doff, Ag + (size_t)(base_m + row) * 512 + kofs + kc * 8);
        CPASYNC16(bbase + doff, Bt + (size_t)(base_n + row) * 512 + kofs + kc * 8);
    }
    CP_COMMIT();
}

__global__ void __launch_bounds__(512, 2) gemm2_bf(const float* __restrict__ bias_all) {
    extern __shared__ float sm[];
    const uint32_t smem_u32 = (uint32_t)__cvta_generic_to_shared(sm);
    const int tid = threadIdx.x, wid = tid >> 5, lane = tid & 31;
    const int kcomp = blockIdx.z, bm = blockIdx.y, bn = blockIdx.x;
    const int base_m = bm * 128, base_n = bn * 128;
    const int wm = (wid >> 2) * 32, wn = (wid & 3) * 32;

    const __nv_bfloat16* Ag = g_h_bf + (size_t)kcomp * BB * HID;
    const __nv_bfloat16* Bt = g_W2t_bf + (size_t)kcomp * AC * HID;

    float acc[2][4][4];
#pragma unroll
    for (int i = 0; i < 2; i++)
#pragma unroll
        for (int j = 0; j < 4; j++)
#pragma unroll
            for (int l = 0; l < 4; l++) acc[i][j][l] = 0.f;

    const int a_hi = (lane >> 4) & 1;
    const int a_r8 = (lane >> 3) & 1;
    uint32_t a_base[2];
#pragma unroll
    for (int mf = 0; mf < 2; mf++) {
        const int row = wm + mf * 16 + a_r8 * 8 + (lane & 7);
        a_base[mf] = (uint32_t)(row * 128 + ((a_hi * 16) ^ ((row & 7) << 4)));
    }
    uint32_t b_row_base[4], b_swz[4];
#pragma unroll
    for (int nf = 0; nf < 4; nf++) {
        const int col = wn + nf * 8 + (lane >> 2);
        b_row_base[nf] = (uint32_t)(col * 128 + (lane & 3) * 4);
        b_swz[nf] = (uint32_t)((col & 7) << 4);
    }

    g2_load(0, tid, smem_u32, Ag, Bt, base_m, base_n);
    g2_load(1, tid, smem_u32, Ag, Bt, base_m, base_n);

    for (int s = 0; s < G2_KSTEPS; s++) {
        if (s + 2 < G2_KSTEPS) {
            g2_load(s + 2, tid, smem_u32, Ag, Bt, base_m, base_n);
            asm volatile("cp.async.wait_group 2;" ::: "memory");
        } else if (s + 1 < G2_KSTEPS) {
            asm volatile("cp.async.wait_group 1;" ::: "memory");
        } else {
            asm volatile("cp.async.wait_group 0;" ::: "memory");
        }
        __syncthreads();

        const uint32_t As = smem_u32 + (s % G2_NSTAGE) * G2_STAGE_B;
        const char* Bsc = (const char*)sm + (s % G2_NSTAGE) * G2_STAGE_B + G2_TILE_B;

#pragma unroll
        for (int sub = 0; sub < 4; sub++) {
            const uint32_t kx = (uint32_t)(sub * 32);
            unsigned a[2][4], b[4][2];
#pragma unroll
            for (int mf = 0; mf < 2; mf++)
                LDSM_X4(a[mf][0], a[mf][1], a[mf][2], a[mf][3], As + (a_base[mf] ^ kx));
#pragma unroll
            for (int nf = 0; nf < 4; nf++) {
                b[nf][0] = *(const unsigned*)(Bsc + b_row_base[nf] + (kx ^ b_swz[nf]));
                b[nf][1] = *(const unsigned*)(Bsc + b_row_base[nf] + ((kx + 16) ^ b_swz[nf]));
            }
#pragma unroll
            for (int mf = 0; mf < 2; mf++)
#pragma unroll
                for (int nf = 0; nf < 4; nf++) mma16816bf(acc[mf][nf], a[mf], b[nf]);
        }
        __syncthreads();
    }

    // ---------------- epilogue: bias, store bf16 logits, fused partial-LSE --
    const float* bias = bias_all + (size_t)kcomp * AC;
    const int q = lane >> 2;
#pragma unroll
    for (int mf = 0; mf < 2; mf++) {
#pragma unroll
        for (int nf = 0; nf < 4; nf++) {
            const int col = base_n + wn + nf * 8 + (lane & 3) * 2;
            const float bv0 = bias[col], bv1 = bias[col + 1];
            acc[mf][nf][0] += bv0; acc[mf][nf][1] += bv1;
            acc[mf][nf][2] += bv0; acc[mf][nf][3] += bv1;
        }
    }
    __nv_bfloat16* outp = g_logits_bf + (size_t)kcomp * BB * AC;
    const int jcol = bn * 4 + (wid & 3);
#pragma unroll
    for (int mf = 0; mf < 2; mf++) {
        const int row = base_m + wm + mf * 16 + q;
#pragma unroll
        for (int nf = 0; nf < 4; nf++) {
            const int col = base_n + wn + nf * 8 + (lane & 3) * 2;
            __nv_bfloat162 p0, p1;
            p0.x = __float2bfloat16(acc[mf][nf][0]);
            p0.y = __float2bfloat16(acc[mf][nf][1]);
            p1.x = __float2bfloat16(acc[mf][nf][2]);
            p1.y = __float2bfloat16(acc[mf][nf][3]);
            *(__nv_bfloat162*)(outp + (size_t)row * AC + col) = p0;
            *(__nv_bfloat162*)(outp + (size_t)(row + 8) * AC + col) = p1;
        }
        float mA = -1e30f, mB = -1e30f;
#pragma unroll
        for (int nf = 0; nf < 4; nf++) {
            mA = fmaxf(mA, fmaxf(acc[mf][nf][0], acc[mf][nf][1]));
            mB = fmaxf(mB, fmaxf(acc[mf][nf][2], acc[mf][nf][3]));
        }
        float sA = 0.f, sB = 0.f;
#pragma unroll
        for (int nf = 0; nf < 4; nf++) {
            sA += __expf(acc[mf][nf][0] - mA) + __expf(acc[mf][nf][1] - mA);
            sB += __expf(acc[mf][nf][2] - mB) + __expf(acc[mf][nf][3] - mB);
        }
#pragma unroll
        for (int o = 1; o <= 2; o <<= 1) {
            float m2 = __shfl_xor_sync(0xFFFFFFFFu, mA, o);
            float s2 = __shfl_xor_sync(0xFFFFFFFFu, sA, o);
            float nm = fmaxf(mA, m2);
            sA = sA * __expf(mA - nm) + s2 * __expf(m2 - nm);
            mA = nm;
            m2 = __shfl_xor_sync(0xFFFFFFFFu, mB, o);
            s2 = __shfl_xor_sync(0xFFFFFFFFu, sB, o);
            nm = fmaxf(mB, m2);
            sB = sB * __expf(mB - nm) + s2 * __expf(m2 - nm);
            mB = nm;
        }
        if ((lane & 3) == 0) {
            const size_t base = ((size_t)kcomp * 32 + jcol) * BB;
            g_pmax[base + row]     = mA;
            g_psum[base + row]     = sA;
            g_pmax[base + row + 8] = mB;
            g_psum[base + row + 8] = sB;
        }
    }
}

// ---------------- finalize lse from 32 partials -----------------------------
__global__ void __launch_bounds__(256) lse_final_kernel() {
    const int r = blockIdx.x * 256 + threadIdx.x;
    const int k = r >> 13, b = r & (BB - 1);
    float mx = -1e30f;
    float pm[32];
#pragma unroll
    for (int j = 0; j < 32; j++) {
        pm[j] = g_pmax[((size_t)k * 32 + j) * BB + b];
        mx = fmaxf(mx, pm[j]);
    }
    float s = 0.f;
#pragma unroll
    for (int j = 0; j < 32; j++)
        s += g_psum[((size_t)k * 32 + j) * BB + b] * __expf(pm[j] - mx);
    g_lse[r] = mx + logf(s);
}

// ---------------- exact action-logit recompute: warp per (k,b) --------------
__global__ void __launch_bounds__(256) alp_kernel(const float* __restrict__ b2_all) {
    const int wid = threadIdx.x >> 5, lane = threadIdx.x & 31;
    const int r = blockIdx.x * 8 + wid;
    const int k = r >> 13, b = r & (BB - 1);
    const int a = g_act[b];
    const float4* h4 = (const float4*)(g_h + ((size_t)k * BB + b) * HID);
    const float4* w4 = (const float4*)(g_W2t_f + ((size_t)k * AC + a) * HID);
    float s = 0.f;
#pragma unroll
    for (int i = 0; i < 4; i++) {
        const float4 hv = h4[lane + i * 32];
        const float4 wv = w4[lane + i * 32];
        s += hv.x * wv.x + hv.y * wv.y + hv.z * wv.z + hv.w * wv.w;
    }
#pragma unroll
    for (int o = 16; o; o >>= 1) s += __shfl_xor_sync(0xFFFFFFFFu, s, o);
    if (lane == 0)
        g_alp[r] = s + b2_all[k * AC + a] - g_lse[r];
}

// ---------------- per-sequence mixture recursion ----------------------------
__global__ void mix_kernel(const float* __restrict__ prior_all, float* __restrict__ out) {
    const int s = blockIdx.x;
    const int lane = threadIdx.x;
    __shared__ float sm_alp[TT * KC];

    for (int i = lane; i < TT * KC; i += 32) {
        const int t = i >> 3, k = i & 7;
        sm_alp[i] = g_alp[k * BB + s * TT + t];
    }
    __syncthreads();

    if (lane < 8) {
        const int k = lane;
        const float prior = prior_all[s * KC + k];
        float cum = 0.f;
        for (int t = 0; t < TT; t++) {
            const float m = prior + cum;
            float mx = m;
#pragma unroll
            for (int o = 4; o; o >>= 1) mx = fmaxf(mx, __shfl_xor_sync(0xFFu, mx, o));
            float se = expf(m - mx);
#pragma unroll
            for (int o = 4; o; o >>= 1) se += __shfl_xor_sync(0xFFu, se, o);
            g_mix[k * BB + s * TT + t] = m - (mx + logf(se));
            cum += sm_alp[t * 8 + k];
        }
        const float m = prior + cum;
        float mx = m;
#pragma unroll
        for (int o = 4; o; o >>= 1) mx = fmaxf(mx, __shfl_xor_sync(0xFFu, mx, o));
        float se = expf(m - mx);
#pragma unroll
        for (int o = 4; o; o >>= 1) se += __shfl_xor_sync(0xFFu, se, o);
        out[(size_t)BB * AC + s * KC + k] = m - (mx + logf(se));
    }
}

// ---------------- final combine: logsumexp over K (bf16 logits) -------------
__global__ void __launch_bounds__(256) combine_kernel(float* __restrict__ out) {
    const int b = blockIdx.x;
    __shared__ float off[KC];
    if (threadIdx.x < KC) {
        const int k = threadIdx.x;
        off[k] = g_mix[k * BB + b] - g_lse[k * BB + b];
    }
    __syncthreads();

    float o[KC];
#pragma unroll
    for (int k = 0; k < KC; k++) o[k] = off[k];

#pragma unroll
    for (int i = 0; i < 2; i++) {
        const int a2 = threadIdx.x + i * 256;       // bf16x2 pair index 0..511
        float2 v[KC];
#pragma unroll
        for (int k = 0; k < KC; k++) {
            const __nv_bfloat162 p = *(const __nv_bfloat162*)
                (g_logits_bf + ((size_t)k * BB + b) * AC + a2 * 2);
            v[k].x = __bfloat162float(p.x) + o[k];
            v[k].y = __bfloat162float(p.y) + o[k];
        }
        float mx0 = v[0].x, mx1 = v[0].y;
#pragma unroll
        for (int k = 1; k < KC; k++) {
            mx0 = fmaxf(mx0, v[k].x);
            mx1 = fmaxf(mx1, v[k].y);
        }
        float s0 = 0.f, s1 = 0.f;
#pragma unroll
        for (int k = 0; k < KC; k++) {
            s0 += __expf(v[k].x - mx0);
            s1 += __expf(v[k].y - mx1);
        }
        *(float2*)(out + (size_t)b * AC + a2 * 2) =
            make_float2(mx0 + logf(s0), mx1 + logf(s1));
    }
}

// ---------------- launcher ---------------------------------------------------
extern "C" void kernel_launch(void* const* d_in, const int* in_sizes, int n_in,
                              void* d_out, int out_size) {
    const float* obs     = (const float*)d_in[0];
    const void*  actions = d_in[1];
    const float* prior   = (const float*)d_in[2];
    const float* W1      = (const float*)d_in[3];
    const float* b1      = (const float*)d_in[4];
    const float* W2      = (const float*)d_in[5];
    const float* b2      = (const float*)d_in[6];
    float* out = (float*)d_out;

    cudaFuncSetAttribute(gemm1_tc,
                         cudaFuncAttributeMaxDynamicSharedMemorySize, SMEM1_BYTES);
    cudaFuncSetAttribute(gemm2_bf,
                         cudaFuncAttributeMaxDynamicSharedMemorySize, SMEM2_BYTES);

    const int n_conv = BB * DIM + KC * DIM * HID;
    convert_kernel<<<(n_conv + 255) / 256, 256>>>(obs, W1);
    transpose_w2_kernel<<<dim3(AC / 32, DIM / 32, KC), dim3(32, 8)>>>(W2);
    prep_actions_kernel<<<1, 1024>>>(actions);

    gemm1_tc<<<dim3(HID / 128, BB / 128, KC), 512, SMEM1_BYTES>>>(b1);
    gemm2_bf<<<dim3(AC / 128, BB / 128, KC), 512, SMEM2_BYTES>>>(b2);

    lse_final_kernel<<<KC * BB / 256, 256>>>();
    alp_kernel<<<KC * BB / 8, 256>>>(b2);
    mix_kernel<<<SQ, 32>>>(prior, out);
    combine_kernel<<<BB, 256>>>(out);
}

// round 15
// speedup vs baseline: 1.3228x; 1.3228x over previous
#include <cuda_runtime.h>
#include <cuda_bf16.h>
#include <cuda_fp16.h>
#include <cstdint>

// Problem constants (fixed by setup_inputs)
#define KC   8
#define DIM  512
#define HID  512
#define AC   1024
#define SQ   64
#define TT   128
#define BB   8192

// ---------------- device scratch --------------------------------------------
__device__ __half        g_obs_h[BB * DIM];                   //   8 MB (fp16)
__device__ __half        g_W1t_h[KC * HID * DIM];             //   8 MB [k][h][d]
__device__ float         g_h[(size_t)KC * BB * HID];          // 128 MB fp32
__device__ __nv_bfloat16 g_h_bf[(size_t)KC * BB * HID];       //  64 MB
__device__ __nv_bfloat16 g_W2t_bf[KC * AC * HID];             //   8 MB [k][a][h]
__device__ float         g_W2t_f[KC * AC * HID];              //  16 MB [k][a][h]
__device__ __nv_bfloat16 g_logits_bf[(size_t)KC * BB * AC];   // 128 MB
__device__ float         g_pmax[KC * 32 * BB];                //   8 MB
__device__ float         g_psum[KC * 32 * BB];                //   8 MB
__device__ float         g_lse[KC * BB];
__device__ float         g_alp[KC * BB];
__device__ float         g_mix[KC * BB];
__device__ int           g_act[BB];

// ---------------- obs fp32 -> fp16 ------------------------------------------
__global__ void convert_obs_kernel(const float* __restrict__ obs) {
    int i = blockIdx.x * blockDim.x + threadIdx.x;
    if (i < BB * DIM) g_obs_h[i] = __float2half(obs[i]);
}

// W1 [k][512 d][512 h] -> [k][h][d] fp16. block (32,8), grid (HID/32, DIM/32, KC)
__global__ void transpose_w1_kernel(const float* __restrict__ W1) {
    __shared__ float t[32][33];
    const int k = blockIdx.z;
    const int c0 = blockIdx.x * 32, r0 = blockIdx.y * 32;   // c over H, r over D
    const float* src = W1 + (size_t)k * DIM * HID;
    const int x = threadIdx.x, y = threadIdx.y;
#pragma unroll
    for (int i = 0; i < 32; i += 8)
        t[y + i][x] = src[(size_t)(r0 + y + i) * HID + c0 + x];
    __syncthreads();
#pragma unroll
    for (int i = 0; i < 32; i += 8)
        g_W1t_h[(size_t)k * HID * DIM + (size_t)(c0 + y + i) * DIM + r0 + x] =
            __float2half(t[x][y + i]);
}

// W2 [k][512 d][1024 a] -> [k][a][d] as bf16 AND fp32. block (32,8), grid (32,16,8)
__global__ void transpose_w2_kernel(const float* __restrict__ W2) {
    __shared__ float t[32][33];
    const int k = blockIdx.z;
    const int c0 = blockIdx.x * 32, r0 = blockIdx.y * 32;   // c over A, r over D
    const float* src = W2 + (size_t)k * DIM * AC;
    const int x = threadIdx.x, y = threadIdx.y;
#pragma unroll
    for (int i = 0; i < 32; i += 8)
        t[y + i][x] = src[(size_t)(r0 + y + i) * AC + c0 + x];
    __syncthreads();
#pragma unroll
    for (int i = 0; i < 32; i += 8) {
        const float v = t[x][y + i];
        const size_t o = (size_t)k * AC * HID + (size_t)(c0 + y + i) * HID + r0 + x;
        g_W2t_f[o]  = v;
        g_W2t_bf[o] = __float2bfloat16(v);
    }
}

// ---------------- actions: detect int32 vs int64, normalize to int32 --------
__global__ void prep_actions_kernel(const void* __restrict__ act) {
    const unsigned long long* p64 = (const unsigned long long*)act;
    int bad = 0;
    for (int i = threadIdx.x; i < BB / 2; i += blockDim.x)
        if (p64[i] > 0xFFFFFFFFull) bad = 1;
    int is32 = __syncthreads_or(bad);
    if (is32) {
        const int* p32 = (const int*)act;
        for (int i = threadIdx.x; i < BB; i += blockDim.x) g_act[i] = p32[i];
    } else {
        const long long* pl = (const long long*)act;
        for (int i = threadIdx.x; i < BB; i += blockDim.x) g_act[i] = (int)pl[i];
    }
}

// ---------------- mma helpers -----------------------------------------------
__device__ __forceinline__ void mma16816f16(float* c, const unsigned* a, const unsigned* b) {
    asm volatile(
        "mma.sync.aligned.m16n8k16.row.col.f32.f16.f16.f32 "
        "{%0,%1,%2,%3}, {%4,%5,%6,%7}, {%8,%9}, {%0,%1,%2,%3};\n"
        : "+f"(c[0]), "+f"(c[1]), "+f"(c[2]), "+f"(c[3])
        : "r"(a[0]), "r"(a[1]), "r"(a[2]), "r"(a[3]), "r"(b[0]), "r"(b[1]));
}
__device__ __forceinline__ void mma16816bf(float* c, const unsigned* a, const unsigned* b) {
    asm volatile(
        "mma.sync.aligned.m16n8k16.row.col.f32.bf16.bf16.f32 "
        "{%0,%1,%2,%3}, {%4,%5,%6,%7}, {%8,%9}, {%0,%1,%2,%3};\n"
        : "+f"(c[0]), "+f"(c[1]), "+f"(c[2]), "+f"(c[3])
        : "r"(a[0]), "r"(a[1]), "r"(a[2]), "r"(a[3]), "r"(b[0]), "r"(b[1]));
}

#define LDSM_X4(r0, r1, r2, r3, addr) \
    asm volatile("ldmatrix.sync.aligned.m8n8.x4.shared.b16 {%0,%1,%2,%3}, [%4];" \
                 : "=r"(r0), "=r"(r1), "=r"(r2), "=r"(r3) : "r"(addr))

#define CPASYNC16(dst, src) \
    asm volatile("cp.async.ca.shared.global [%0], [%1], 16;" :: "r"(dst), "l"(src))
#define CP_COMMIT() asm volatile("cp.async.commit_group;" ::: "memory")

// ============================================================================
// Shared 16-bit GEMM geometry (clone of proven r13 gemm2_bf):
// CTA tile 128x128, 256 thr = 8 warps (2m x 4n), warp 64x32.
// A tile [128 m][64 k] K-major swizzled, LDSM.x4; B tile [128 n][64 k] same
// layout, scalar 32-bit k-pair LDS. 8 K-steps of 64.
// ============================================================================
#define G_NSTAGE  3
#define G_KSTEPS  8
#define G_TILE_B  16384
#define G_STAGE_B (2 * G_TILE_B)
#define SMEM_BYTES (G_NSTAGE * G_STAGE_B)    // 98304

template <typename T>
__device__ __forceinline__ void g_load(int s, int tid, uint32_t smem_u32,
                                       const T* Ag, const T* Bt,
                                       int base_m, int base_n) {
    const uint32_t abase = smem_u32 + (s % G_NSTAGE) * G_STAGE_B;
    const uint32_t bbase = abase + G_TILE_B;
    const int kofs = s * 64;
#pragma unroll
    for (int i = 0; i < 4; i++) {
        const int idx = tid + 256 * i;
        const int row = idx >> 3, kc = idx & 7;
        const uint32_t doff = (uint32_t)(row * 128 + ((kc * 16) ^ ((row & 7) << 4)));
        CPASYNC16(abase + doff, Ag + (size_t)(base_m + row) * 512 + kofs + kc * 8);
        CPASYNC16(bbase + doff, Bt + (size_t)(base_n + row) * 512 + kofs + kc * 8);
    }
    CP_COMMIT();
}

// ============================================================================
// GEMM1 (fp16): h = relu(obs @ W1t^T + b1)  -> h fp32 + h bf16
// ============================================================================
__global__ void __launch_bounds__(256, 2) gemm1_h(const float* __restrict__ bias_all) {
    extern __shared__ float sm[];
    const uint32_t smem_u32 = (uint32_t)__cvta_generic_to_shared(sm);
    const int tid = threadIdx.x, wid = tid >> 5, lane = tid & 31;
    const int kcomp = blockIdx.z, bm = blockIdx.y, bn = blockIdx.x;
    const int base_m = bm * 128, base_n = bn * 128;
    const int wm = (wid >> 2) * 64, wn = (wid & 3) * 32;

    const __half* Ag = g_obs_h;
    const __half* Bt = g_W1t_h + (size_t)kcomp * HID * DIM;

    float acc[4][4][4];
#pragma unroll
    for (int i = 0; i < 4; i++)
#pragma unroll
        for (int j = 0; j < 4; j++)
#pragma unroll
            for (int l = 0; l < 4; l++) acc[i][j][l] = 0.f;

    const int a_hi = (lane >> 4) & 1;
    const int a_r8 = (lane >> 3) & 1;
    uint32_t a_base[4];
#pragma unroll
    for (int mf = 0; mf < 4; mf++) {
        const int row = wm + mf * 16 + a_r8 * 8 + (lane & 7);
        a_base[mf] = (uint32_t)(row * 128 + ((a_hi * 16) ^ ((row & 7) << 4)));
    }
    uint32_t b_row_base[4], b_swz[4];
#pragma unroll
    for (int nf = 0; nf < 4; nf++) {
        const int col = wn + nf * 8 + (lane >> 2);
        b_row_base[nf] = (uint32_t)(col * 128 + (lane & 3) * 4);
        b_swz[nf] = (uint32_t)((col & 7) << 4);
    }

    g_load(0, tid, smem_u32, Ag, Bt, base_m, base_n);
    g_load(1, tid, smem_u32, Ag, Bt, base_m, base_n);

    for (int s = 0; s < G_KSTEPS; s++) {
        if (s + 2 < G_KSTEPS) {
            g_load(s + 2, tid, smem_u32, Ag, Bt, base_m, base_n);
            asm volatile("cp.async.wait_group 2;" ::: "memory");
        } else if (s + 1 < G_KSTEPS) {
            asm volatile("cp.async.wait_group 1;" ::: "memory");
        } else {
            asm volatile("cp.async.wait_group 0;" ::: "memory");
        }
        __syncthreads();

        const uint32_t As = smem_u32 + (s % G_NSTAGE) * G_STAGE_B;
        const char* Bsc = (const char*)sm + (s % G_NSTAGE) * G_STAGE_B + G_TILE_B;

#pragma unroll
        for (int sub = 0; sub < 4; sub++) {
            const uint32_t kx = (uint32_t)(sub * 32);
            unsigned a[4][4], b[4][2];
#pragma unroll
            for (int mf = 0; mf < 4; mf++)
                LDSM_X4(a[mf][0], a[mf][1], a[mf][2], a[mf][3], As + (a_base[mf] ^ kx));
#pragma unroll
            for (int nf = 0; nf < 4; nf++) {
                b[nf][0] = *(const unsigned*)(Bsc + b_row_base[nf] + (kx ^ b_swz[nf]));
                b[nf][1] = *(const unsigned*)(Bsc + b_row_base[nf] + ((kx + 16) ^ b_swz[nf]));
            }
#pragma unroll
            for (int mf = 0; mf < 4; mf++)
#pragma unroll
                for (int nf = 0; nf < 4; nf++) mma16816f16(acc[mf][nf], a[mf], b[nf]);
        }
        __syncthreads();
    }

    // epilogue: bias + relu -> h fp32 + h bf16
    const float* bias = bias_all + (size_t)kcomp * HID;
    const int q = lane >> 2;
    float* outp = g_h + (size_t)kcomp * BB * HID;
    __nv_bfloat16* outb = g_h_bf + (size_t)kcomp * BB * HID;
#pragma unroll
    for (int mf = 0; mf < 4; mf++) {
        const int row = base_m + wm + mf * 16 + q;
#pragma unroll
        for (int nf = 0; nf < 4; nf++) {
            const int col = base_n + wn + nf * 8 + (lane & 3) * 2;
            const float bv0 = bias[col], bv1 = bias[col + 1];
            float v0 = fmaxf(acc[mf][nf][0] + bv0, 0.f);
            float v1 = fmaxf(acc[mf][nf][1] + bv1, 0.f);
            float v2 = fmaxf(acc[mf][nf][2] + bv0, 0.f);
            float v3 = fmaxf(acc[mf][nf][3] + bv1, 0.f);
            *(float2*)(outp + (size_t)row * HID + col) = make_float2(v0, v1);
            *(float2*)(outp + (size_t)(row + 8) * HID + col) = make_float2(v2, v3);
            __nv_bfloat162 q0, q1;
            q0.x = __float2bfloat16(v0); q0.y = __float2bfloat16(v1);
            q1.x = __float2bfloat16(v2); q1.y = __float2bfloat16(v3);
            *(__nv_bfloat162*)(outb + (size_t)row * HID + col) = q0;
            *(__nv_bfloat162*)(outb + (size_t)(row + 8) * HID + col) = q1;
        }
    }
}

// ============================================================================
// GEMM2 (bf16, byte-identical to r13): logits_bf = h_bf @ W2t_bf^T + b2,
// fused partial-LSE
// ============================================================================
__global__ void __launch_bounds__(256, 2) gemm2_bf(const float* __restrict__ bias_all) {
    extern __shared__ float sm[];
    const uint32_t smem_u32 = (uint32_t)__cvta_generic_to_shared(sm);
    const int tid = threadIdx.x, wid = tid >> 5, lane = tid & 31;
    const int kcomp = blockIdx.z, bm = blockIdx.y, bn = blockIdx.x;
    const int base_m = bm * 128, base_n = bn * 128;
    const int wm = (wid >> 2) * 64, wn = (wid & 3) * 32;

    const __nv_bfloat16* Ag = g_h_bf + (size_t)kcomp * BB * HID;
    const __nv_bfloat16* Bt = g_W2t_bf + (size_t)kcomp * AC * HID;

    float acc[4][4][4];
#pragma unroll
    for (int i = 0; i < 4; i++)
#pragma unroll
        for (int j = 0; j < 4; j++)
#pragma unroll
            for (int l = 0; l < 4; l++) acc[i][j][l] = 0.f;

    const int a_hi = (lane >> 4) & 1;
    const int a_r8 = (lane >> 3) & 1;
    uint32_t a_base[4];
#pragma unroll
    for (int mf = 0; mf < 4; mf++) {
        const int row = wm + mf * 16 + a_r8 * 8 + (lane & 7);
        a_base[mf] = (uint32_t)(row * 128 + ((a_hi * 16) ^ ((row & 7) << 4)));
    }
    uint32_t b_row_base[4], b_swz[4];
#pragma unroll
    for (int nf = 0; nf < 4; nf++) {
        const int col = wn + nf * 8 + (lane >> 2);
        b_row_base[nf] = (uint32_t)(col * 128 + (lane & 3) * 4);
        b_swz[nf] = (uint32_t)((col & 7) << 4);
    }

    g_load(0, tid, smem_u32, Ag, Bt, base_m, base_n);
    g_load(1, tid, smem_u32, Ag, Bt, base_m, base_n);

    for (int s = 0; s < G_KSTEPS; s++) {
        if (s + 2 < G_KSTEPS) {
            g_load(s + 2, tid, smem_u32, Ag, Bt, base_m, base_n);
            asm volatile("cp.async.wait_group 2;" ::: "memory");
        } else if (s + 1 < G_KSTEPS) {
            asm volatile("cp.async.wait_group 1;" ::: "memory");
        } else {
            asm volatile("cp.async.wait_group 0;" ::: "memory");
        }
        __syncthreads();

        const uint32_t As = smem_u32 + (s % G_NSTAGE) * G_STAGE_B;
        const char* Bsc = (const char*)sm + (s % G_NSTAGE) * G_STAGE_B + G_TILE_B;

#pragma unroll
        for (int sub = 0; sub < 4; sub++) {
            const uint32_t kx = (uint32_t)(sub * 32);
            unsigned a[4][4], b[4][2];
#pragma unroll
            for (int mf = 0; mf < 4; mf++)
                LDSM_X4(a[mf][0], a[mf][1], a[mf][2], a[mf][3], As + (a_base[mf] ^ kx));
#pragma unroll
            for (int nf = 0; nf < 4; nf++) {
                b[nf][0] = *(const unsigned*)(Bsc + b_row_base[nf] + (kx ^ b_swz[nf]));
                b[nf][1] = *(const unsigned*)(Bsc + b_row_base[nf] + ((kx + 16) ^ b_swz[nf]));
            }
#pragma unroll
            for (int mf = 0; mf < 4; mf++)
#pragma unroll
                for (int nf = 0; nf < 4; nf++) mma16816bf(acc[mf][nf], a[mf], b[nf]);
        }
        __syncthreads();
    }

    // ---------------- epilogue: bias, store bf16 logits, fused partial-LSE --
    const float* bias = bias_all + (size_t)kcomp * AC;
    const int q = lane >> 2;
#pragma unroll
    for (int mf = 0; mf < 4; mf++) {
#pragma unroll
        for (int nf = 0; nf < 4; nf++) {
            const int col = base_n + wn + nf * 8 + (lane & 3) * 2;
            const float bv0 = bias[col], bv1 = bias[col + 1];
            acc[mf][nf][0] += bv0; acc[mf][nf][1] += bv1;
            acc[mf][nf][2] += bv0; acc[mf][nf][3] += bv1;
        }
    }
    __nv_bfloat16* outp = g_logits_bf + (size_t)kcomp * BB * AC;
    const int jcol = bn * 4 + (wid & 3);
#pragma unroll
    for (int mf = 0; mf < 4; mf++) {
        const int row = base_m + wm + mf * 16 + q;
#pragma unroll
        for (int nf = 0; nf < 4; nf++) {
            const int col = base_n + wn + nf * 8 + (lane & 3) * 2;
            __nv_bfloat162 p0, p1;
            p0.x = __float2bfloat16(acc[mf][nf][0]);
            p0.y = __float2bfloat16(acc[mf][nf][1]);
            p1.x = __float2bfloat16(acc[mf][nf][2]);
            p1.y = __float2bfloat16(acc[mf][nf][3]);
            *(__nv_bfloat162*)(outp + (size_t)row * AC + col) = p0;
            *(__nv_bfloat162*)(outp + (size_t)(row + 8) * AC + col) = p1;
        }
        float mA = -1e30f, mB = -1e30f;
#pragma unroll
        for (int nf = 0; nf < 4; nf++) {
            mA = fmaxf(mA, fmaxf(acc[mf][nf][0], acc[mf][nf][1]));
            mB = fmaxf(mB, fmaxf(acc[mf][nf][2], acc[mf][nf][3]));
        }
        float sA = 0.f, sB = 0.f;
#pragma unroll
        for (int nf = 0; nf < 4; nf++) {
            sA += __expf(acc[mf][nf][0] - mA) + __expf(acc[mf][nf][1] - mA);
            sB += __expf(acc[mf][nf][2] - mB) + __expf(acc[mf][nf][3] - mB);
        }
#pragma unroll
        for (int o = 1; o <= 2; o <<= 1) {
            float m2 = __shfl_xor_sync(0xFFFFFFFFu, mA, o);
            float s2 = __shfl_xor_sync(0xFFFFFFFFu, sA, o);
            float nm = fmaxf(mA, m2);
            sA = sA * __expf(mA - nm) + s2 * __expf(m2 - nm);
            mA = nm;
            m2 = __shfl_xor_sync(0xFFFFFFFFu, mB, o);
            s2 = __shfl_xor_sync(0xFFFFFFFFu, sB, o);
            nm = fmaxf(mB, m2);
            sB = sB * __expf(mB - nm) + s2 * __expf(m2 - nm);
            mB = nm;
        }
        if ((lane & 3) == 0) {
            const size_t base = ((size_t)kcomp * 32 + jcol) * BB;
            g_pmax[base + row]     = mA;
            g_psum[base + row]     = sA;
            g_pmax[base + row + 8] = mB;
            g_psum[base + row + 8] = sB;
        }
    }
}

// ---------------- finalize lse from 32 partials -----------------------------
__global__ void __launch_bounds__(256) lse_final_kernel() {
    const int r = blockIdx.x * 256 + threadIdx.x;
    const int k = r >> 13, b = r & (BB - 1);
    float mx = -1e30f;
    float pm[32];
#pragma unroll
    for (int j = 0; j < 32; j++) {
        pm[j] = g_pmax[((size_t)k * 32 + j) * BB + b];
        mx = fmaxf(mx, pm[j]);
    }
    float s = 0.f;
#pragma unroll
    for (int j = 0; j < 32; j++)
        s += g_psum[((size_t)k * 32 + j) * BB + b] * __expf(pm[j] - mx);
    g_lse[r] = mx + logf(s);
}

// ---------------- exact action-logit recompute: warp per (k,b) --------------
__global__ void __launch_bounds__(256) alp_kernel(const float* __restrict__ b2_all) {
    const int wid = threadIdx.x >> 5, lane = threadIdx.x & 31;
    const int r = blockIdx.x * 8 + wid;
    const int k = r >> 13, b = r & (BB - 1);
    const int a = g_act[b];
    const float4* h4 = (const float4*)(g_h + ((size_t)k * BB + b) * HID);
    const float4* w4 = (const float4*)(g_W2t_f + ((size_t)k * AC + a) * HID);
    float s = 0.f;
#pragma unroll
    for (int i = 0; i < 4; i++) {
        const float4 hv = h4[lane + i * 32];
        const float4 wv = w4[lane + i * 32];
        s += hv.x * wv.x + hv.y * wv.y + hv.z * wv.z + hv.w * wv.w;
    }
#pragma unroll
    for (int o = 16; o; o >>= 1) s += __shfl_xor_sync(0xFFFFFFFFu, s, o);
    if (lane == 0)
        g_alp[r] = s + b2_all[k * AC + a] - g_lse[r];
}

// ---------------- per-sequence mixture recursion ----------------------------
__global__ void mix_kernel(const float* __restrict__ prior_all, float* __restrict__ out) {
    const int s = blockIdx.x;
    const int lane = threadIdx.x;
    __shared__ float sm_alp[TT * KC];

    for (int i = lane; i < TT * KC; i += 32) {
        const int t = i >> 3, k = i & 7;
        sm_alp[i] = g_alp[k * BB + s * TT + t];
    }
    __syncthreads();

    if (lane < 8) {
        const int k = lane;
        const float prior = prior_all[s * KC + k];
        float cum = 0.f;
        for (int t = 0; t < TT; t++) {
            const float m = prior + cum;
            float mx = m;
#pragma unroll
            for (int o = 4; o; o >>= 1) mx = fmaxf(mx, __shfl_xor_sync(0xFFu, mx, o));
            float se = expf(m - mx);
#pragma unroll
            for (int o = 4; o; o >>= 1) se += __shfl_xor_sync(0xFFu, se, o);
            g_mix[k * BB + s * TT + t] = m - (mx + logf(se));
            cum += sm_alp[t * 8 + k];
        }
        const float m = prior + cum;
        float mx = m;
#pragma unroll
        for (int o = 4; o; o >>= 1) mx = fmaxf(mx, __shfl_xor_sync(0xFFu, mx, o));
        float se = expf(m - mx);
#pragma unroll
        for (int o = 4; o; o >>= 1) se += __shfl_xor_sync(0xFFu, se, o);
        out[(size_t)BB * AC + s * KC + k] = m - (mx + logf(se));
    }
}

// ---------------- final combine: logsumexp over K (bf16 logits) -------------
__global__ void __launch_bounds__(256) combine_kernel(float* __restrict__ out) {
    const int b = blockIdx.x;
    __shared__ float off[KC];
    if (threadIdx.x < KC) {
        const int k = threadIdx.x;
        off[k] = g_mix[k * BB + b] - g_lse[k * BB + b];
    }
    __syncthreads();

    float o[KC];
#pragma unroll
    for (int k = 0; k < KC; k++) o[k] = off[k];

#pragma unroll
    for (int i = 0; i < 2; i++) {
        const int a2 = threadIdx.x + i * 256;       // bf16x2 pair index 0..511
        float2 v[KC];
#pragma unroll
        for (int k = 0; k < KC; k++) {
            const __nv_bfloat162 p = *(const __nv_bfloat162*)
                (g_logits_bf + ((size_t)k * BB + b) * AC + a2 * 2);
            v[k].x = __bfloat162float(p.x) + o[k];
            v[k].y = __bfloat162float(p.y) + o[k];
        }
        float mx0 = v[0].x, mx1 = v[0].y;
#pragma unroll
        for (int k = 1; k < KC; k++) {
            mx0 = fmaxf(mx0, v[k].x);
            mx1 = fmaxf(mx1, v[k].y);
        }
        float s0 = 0.f, s1 = 0.f;
#pragma unroll
        for (int k = 0; k < KC; k++) {
            s0 += __expf(v[k].x - mx0);
            s1 += __expf(v[k].y - mx1);
        }
        *(float2*)(out + (size_t)b * AC + a2 * 2) =
            make_float2(mx0 + logf(s0), mx1 + logf(s1));
    }
}

// ---------------- launcher ---------------------------------------------------
extern "C" void kernel_launch(void* const* d_in, const int* in_sizes, int n_in,
                              void* d_out, int out_size) {
    const float* obs     = (const float*)d_in[0];
    const void*  actions = d_in[1];
    const float* prior   = (const float*)d_in[2];
    const float* W1      = (const float*)d_in[3];
    const float* b1      = (const float*)d_in[4];
    const float* W2      = (const float*)d_in[5];
    const float* b2      = (const float*)d_in[6];
    float* out = (float*)d_out;

    cudaFuncSetAttribute(gemm1_h,
                         cudaFuncAttributeMaxDynamicSharedMemorySize, SMEM_BYTES);
    cudaFuncSetAttribute(gemm2_bf,
                         cudaFuncAttributeMaxDynamicSharedMemorySize, SMEM_BYTES);

    convert_obs_kernel<<<(BB * DIM + 255) / 256, 256>>>(obs);
    transpose_w1_kernel<<<dim3(HID / 32, DIM / 32, KC), dim3(32, 8)>>>(W1);
    transpose_w2_kernel<<<dim3(AC / 32, DIM / 32, KC), dim3(32, 8)>>>(W2);
    prep_actions_kernel<<<1, 1024>>>(actions);

    gemm1_h<<<dim3(HID / 128, BB / 128, KC), 256, SMEM_BYTES>>>(b1);
    gemm2_bf<<<dim3(AC / 128, BB / 128, KC), 256, SMEM_BYTES>>>(b2);

    lse_final_kernel<<<KC * BB / 256, 256>>>();
    alp_kernel<<<KC * BB / 8, 256>>>(b2);
    mix_kernel<<<SQ, 32>>>(prior, out);
    combine_kernel<<<BB, 256>>>(out);
}

// round 17
// speedup vs baseline: 1.3790x; 1.0425x over previous
#include <cuda_runtime.h>
#include <cuda_bf16.h>
#include <cuda_fp16.h>
#include <cstdint>

// Problem constants (fixed by setup_inputs)
#define KC   8
#define DIM  512
#define HID  512
#define AC   1024
#define SQ   64
#define TT   128
#define BB   8192

// ---------------- device scratch --------------------------------------------
__device__ __half        g_obs_h[BB * DIM];                   //   8 MB (fp16)
__device__ __half        g_W1t_h[KC * HID * DIM];             //   8 MB [k][h][d]
__device__ __half        g_h_h[(size_t)KC * BB * HID];        //  64 MB (fp16 h)
__device__ __half        g_W2t_h[KC * AC * HID];              //   8 MB [k][a][h]
__device__ float         g_W2t_f[KC * AC * HID];              //  16 MB [k][a][h]
__device__ __nv_bfloat16 g_logits_bf[(size_t)KC * BB * AC];   // 128 MB
__device__ float         g_pmax[KC * 32 * BB];                //   8 MB
__device__ float         g_psum[KC * 32 * BB];                //   8 MB
__device__ float         g_lse[KC * BB];
__device__ float         g_alp[KC * BB];
__device__ float         g_mix[KC * BB];
__device__ int           g_act[BB];

// ---------------- obs fp32 -> fp16 ------------------------------------------
__global__ void convert_obs_kernel(const float* __restrict__ obs) {
    int i = blockIdx.x * blockDim.x + threadIdx.x;
    if (i < BB * DIM) g_obs_h[i] = __float2half(obs[i]);
}

// W1 [k][512 d][512 h] -> [k][h][d] fp16. block (32,8), grid (HID/32, DIM/32, KC)
__global__ void transpose_w1_kernel(const float* __restrict__ W1) {
    __shared__ float t[32][33];
    const int k = blockIdx.z;
    const int c0 = blockIdx.x * 32, r0 = blockIdx.y * 32;   // c over H, r over D
    const float* src = W1 + (size_t)k * DIM * HID;
    const int x = threadIdx.x, y = threadIdx.y;
#pragma unroll
    for (int i = 0; i < 32; i += 8)
        t[y + i][x] = src[(size_t)(r0 + y + i) * HID + c0 + x];
    __syncthreads();
#pragma unroll
    for (int i = 0; i < 32; i += 8)
        g_W1t_h[(size_t)k * HID * DIM + (size_t)(c0 + y + i) * DIM + r0 + x] =
            __float2half(t[x][y + i]);
}

// W2 [k][512 d][1024 a] -> [k][a][d] as fp16 AND fp32. block (32,8), grid (32,16,8)
__global__ void transpose_w2_kernel(const float* __restrict__ W2) {
    __shared__ float t[32][33];
    const int k = blockIdx.z;
    const int c0 = blockIdx.x * 32, r0 = blockIdx.y * 32;   // c over A, r over D
    const float* src = W2 + (size_t)k * DIM * AC;
    const int x = threadIdx.x, y = threadIdx.y;
#pragma unroll
    for (int i = 0; i < 32; i += 8)
        t[y + i][x] = src[(size_t)(r0 + y + i) * AC + c0 + x];
    __syncthreads();
#pragma unroll
    for (int i = 0; i < 32; i += 8) {
        const float v = t[x][y + i];
        const size_t o = (size_t)k * AC * HID + (size_t)(c0 + y + i) * HID + r0 + x;
        g_W2t_f[o] = v;
        g_W2t_h[o] = __float2half(v);
    }
}

// ---------------- actions: detect int32 vs int64, normalize to int32 --------
__global__ void prep_actions_kernel(const void* __restrict__ act) {
    const unsigned long long* p64 = (const unsigned long long*)act;
    int bad = 0;
    for (int i = threadIdx.x; i < BB / 2; i += blockDim.x)
        if (p64[i] > 0xFFFFFFFFull) bad = 1;
    int is32 = __syncthreads_or(bad);
    if (is32) {
        const int* p32 = (const int*)act;
        for (int i = threadIdx.x; i < BB; i += blockDim.x) g_act[i] = p32[i];
    } else {
        const long long* pl = (const long long*)act;
        for (int i = threadIdx.x; i < BB; i += blockDim.x) g_act[i] = (int)pl[i];
    }
}

// ---------------- mma helper (fp16) -----------------------------------------
__device__ __forceinline__ void mma16816f16(float* c, const unsigned* a, const unsigned* b) {
    asm volatile(
        "mma.sync.aligned.m16n8k16.row.col.f32.f16.f16.f32 "
        "{%0,%1,%2,%3}, {%4,%5,%6,%7}, {%8,%9}, {%0,%1,%2,%3};\n"
        : "+f"(c[0]), "+f"(c[1]), "+f"(c[2]), "+f"(c[3])
        : "r"(a[0]), "r"(a[1]), "r"(a[2]), "r"(a[3]), "r"(b[0]), "r"(b[1]));
}

#define LDSM_X4(r0, r1, r2, r3, addr) \
    asm volatile("ldmatrix.sync.aligned.m8n8.x4.shared.b16 {%0,%1,%2,%3}, [%4];" \
                 : "=r"(r0), "=r"(r1), "=r"(r2), "=r"(r3) : "r"(addr))

#define CPASYNC16(dst, src) \
    asm volatile("cp.async.ca.shared.global [%0], [%1], 16;" :: "r"(dst), "l"(src))
#define CP_COMMIT() asm volatile("cp.async.commit_group;" ::: "memory")

// ============================================================================
// Shared 16-bit GEMM geometry (proven): CTA 128x128, 256 thr = 8 warps
// (2m x 4n), warp 64x32. A tile [128 m][64 k] K-major swizzled, LDSM.x4;
// B tile [128 n][64 k] same layout, scalar 32-bit k-pair LDS. 8 K-steps.
// ============================================================================
#define G_NSTAGE  3
#define G_KSTEPS  8
#define G_TILE_B  16384
#define G_STAGE_B (2 * G_TILE_B)
#define SMEM_BYTES (G_NSTAGE * G_STAGE_B)    // 98304

__device__ __forceinline__ void g_load(int s, int tid, uint32_t smem_u32,
                                       const __half* Ag, const __half* Bt,
                                       int base_m, int base_n) {
    const uint32_t abase = smem_u32 + (s % G_NSTAGE) * G_STAGE_B;
    const uint32_t bbase = abase + G_TILE_B;
    const int kofs = s * 64;
#pragma unroll
    for (int i = 0; i < 4; i++) {
        const int idx = tid + 256 * i;
        const int row = idx >> 3, kc = idx & 7;
        const uint32_t doff = (uint32_t)(row * 128 + ((kc * 16) ^ ((row & 7) << 4)));
        CPASYNC16(abase + doff, Ag + (size_t)(base_m + row) * 512 + kofs + kc * 8);
        CPASYNC16(bbase + doff, Bt + (size_t)(base_n + row) * 512 + kofs + kc * 8);
    }
    CP_COMMIT();
}

// ============================================================================
// GEMM1 (fp16): h_h = fp16(relu(obs @ W1t^T + b1))
// ============================================================================
__global__ void __launch_bounds__(256, 2) gemm1_h(const float* __restrict__ bias_all) {
    extern __shared__ float sm[];
    const uint32_t smem_u32 = (uint32_t)__cvta_generic_to_shared(sm);
    const int tid = threadIdx.x, wid = tid >> 5, lane = tid & 31;
    const int kcomp = blockIdx.z, bm = blockIdx.y, bn = blockIdx.x;
    const int base_m = bm * 128, base_n = bn * 128;
    const int wm = (wid >> 2) * 64, wn = (wid & 3) * 32;

    const __half* Ag = g_obs_h;
    const __half* Bt = g_W1t_h + (size_t)kcomp * HID * DIM;

    float acc[4][4][4];
#pragma unroll
    for (int i = 0; i < 4; i++)
#pragma unroll
        for (int j = 0; j < 4; j++)
#pragma unroll
            for (int l = 0; l < 4; l++) acc[i][j][l] = 0.f;

    const int a_hi = (lane >> 4) & 1;
    const int a_r8 = (lane >> 3) & 1;
    uint32_t a_base[4];
#pragma unroll
    for (int mf = 0; mf < 4; mf++) {
        const int row = wm + mf * 16 + a_r8 * 8 + (lane & 7);
        a_base[mf] = (uint32_t)(row * 128 + ((a_hi * 16) ^ ((row & 7) << 4)));
    }
    uint32_t b_row_base[4], b_swz[4];
#pragma unroll
    for (int nf = 0; nf < 4; nf++) {
        const int col = wn + nf * 8 + (lane >> 2);
        b_row_base[nf] = (uint32_t)(col * 128 + (lane & 3) * 4);
        b_swz[nf] = (uint32_t)((col & 7) << 4);
    }

    g_load(0, tid, smem_u32, Ag, Bt, base_m, base_n);
    g_load(1, tid, smem_u32, Ag, Bt, base_m, base_n);

    for (int s = 0; s < G_KSTEPS; s++) {
        if (s + 2 < G_KSTEPS) {
            g_load(s + 2, tid, smem_u32, Ag, Bt, base_m, base_n);
            asm volatile("cp.async.wait_group 2;" ::: "memory");
        } else if (s + 1 < G_KSTEPS) {
            asm volatile("cp.async.wait_group 1;" ::: "memory");
        } else {
            asm volatile("cp.async.wait_group 0;" ::: "memory");
        }
        __syncthreads();

        const uint32_t As = smem_u32 + (s % G_NSTAGE) * G_STAGE_B;
        const char* Bsc = (const char*)sm + (s % G_NSTAGE) * G_STAGE_B + G_TILE_B;

#pragma unroll
        for (int sub = 0; sub < 4; sub++) {
            const uint32_t kx = (uint32_t)(sub * 32);
            unsigned a[4][4], b[4][2];
#pragma unroll
            for (int mf = 0; mf < 4; mf++)
                LDSM_X4(a[mf][0], a[mf][1], a[mf][2], a[mf][3], As + (a_base[mf] ^ kx));
#pragma unroll
            for (int nf = 0; nf < 4; nf++) {
                b[nf][0] = *(const unsigned*)(Bsc + b_row_base[nf] + (kx ^ b_swz[nf]));
                b[nf][1] = *(const unsigned*)(Bsc + b_row_base[nf] + ((kx + 16) ^ b_swz[nf]));
            }
#pragma unroll
            for (int mf = 0; mf < 4; mf++)
#pragma unroll
                for (int nf = 0; nf < 4; nf++) mma16816f16(acc[mf][nf], a[mf], b[nf]);
        }
        __syncthreads();
    }

    // epilogue: bias + relu -> h fp16 (single copy)
    const float* bias = bias_all + (size_t)kcomp * HID;
    const int q = lane >> 2;
    __half* outh = g_h_h + (size_t)kcomp * BB * HID;
#pragma unroll
    for (int mf = 0; mf < 4; mf++) {
        const int row = base_m + wm + mf * 16 + q;
#pragma unroll
        for (int nf = 0; nf < 4; nf++) {
            const int col = base_n + wn + nf * 8 + (lane & 3) * 2;
            const float bv0 = bias[col], bv1 = bias[col + 1];
            __half2 h0, h1;
            h0.x = __float2half(fmaxf(acc[mf][nf][0] + bv0, 0.f));
            h0.y = __float2half(fmaxf(acc[mf][nf][1] + bv1, 0.f));
            h1.x = __float2half(fmaxf(acc[mf][nf][2] + bv0, 0.f));
            h1.y = __float2half(fmaxf(acc[mf][nf][3] + bv1, 0.f));
            *(__half2*)(outh + (size_t)row * HID + col) = h0;
            *(__half2*)(outh + (size_t)(row + 8) * HID + col) = h1;
        }
    }
}

// ============================================================================
// GEMM2 (fp16): logits_bf = bf16(h_h @ W2t_h^T + b2), fused partial-LSE
// ============================================================================
__global__ void __launch_bounds__(256, 2) gemm2_h(const float* __restrict__ bias_all) {
    extern __shared__ float sm[];
    const uint32_t smem_u32 = (uint32_t)__cvta_generic_to_shared(sm);
    const int tid = threadIdx.x, wid = tid >> 5, lane = tid & 31;
    const int kcomp = blockIdx.z, bm = blockIdx.y, bn = blockIdx.x;
    const int base_m = bm * 128, base_n = bn * 128;
    const int wm = (wid >> 2) * 64, wn = (wid & 3) * 32;

    const __half* Ag = g_h_h + (size_t)kcomp * BB * HID;
    const __half* Bt = g_W2t_h + (size_t)kcomp * AC * HID;

    float acc[4][4][4];
#pragma unroll
    for (int i = 0; i < 4; i++)
#pragma unroll
        for (int j = 0; j < 4; j++)
#pragma unroll
            for (int l = 0; l < 4; l++) acc[i][j][l] = 0.f;

    const int a_hi = (lane >> 4) & 1;
    const int a_r8 = (lane >> 3) & 1;
    uint32_t a_base[4];
#pragma unroll
    for (int mf = 0; mf < 4; mf++) {
        const int row = wm + mf * 16 + a_r8 * 8 + (lane & 7);
        a_base[mf] = (uint32_t)(row * 128 + ((a_hi * 16) ^ ((row & 7) << 4)));
    }
    uint32_t b_row_base[4], b_swz[4];
#pragma unroll
    for (int nf = 0; nf < 4; nf++) {
        const int col = wn + nf * 8 + (lane >> 2);
        b_row_base[nf] = (uint32_t)(col * 128 + (lane & 3) * 4);
        b_swz[nf] = (uint32_t)((col & 7) << 4);
    }

    g_load(0, tid, smem_u32, Ag, Bt, base_m, base_n);
    g_load(1, tid, smem_u32, Ag, Bt, base_m, base_n);

    for (int s = 0; s < G_KSTEPS; s++) {
        if (s + 2 < G_KSTEPS) {
            g_load(s + 2, tid, smem_u32, Ag, Bt, base_m, base_n);
            asm volatile("cp.async.wait_group 2;" ::: "memory");
        } else if (s + 1 < G_KSTEPS) {
            asm volatile("cp.async.wait_group 1;" ::: "memory");
        } else {
            asm volatile("cp.async.wait_group 0;" ::: "memory");
        }
        __syncthreads();

        const uint32_t As = smem_u32 + (s % G_NSTAGE) * G_STAGE_B;
        const char* Bsc = (const char*)sm + (s % G_NSTAGE) * G_STAGE_B + G_TILE_B;

#pragma unroll
        for (int sub = 0; sub < 4; sub++) {
            const uint32_t kx = (uint32_t)(sub * 32);
            unsigned a[4][4], b[4][2];
#pragma unroll
            for (int mf = 0; mf < 4; mf++)
                LDSM_X4(a[mf][0], a[mf][1], a[mf][2], a[mf][3], As + (a_base[mf] ^ kx));
#pragma unroll
            for (int nf = 0; nf < 4; nf++) {
                b[nf][0] = *(const unsigned*)(Bsc + b_row_base[nf] + (kx ^ b_swz[nf]));
                b[nf][1] = *(const unsigned*)(Bsc + b_row_base[nf] + ((kx + 16) ^ b_swz[nf]));
            }
#pragma unroll
            for (int mf = 0; mf < 4; mf++)
#pragma unroll
                for (int nf = 0; nf < 4; nf++) mma16816f16(acc[mf][nf], a[mf], b[nf]);
        }
        __syncthreads();
    }

    // ---------------- epilogue: bias, store bf16 logits, fused partial-LSE --
    const float* bias = bias_all + (size_t)kcomp * AC;
    const int q = lane >> 2;
#pragma unroll
    for (int mf = 0; mf < 4; mf++) {
#pragma unroll
        for (int nf = 0; nf < 4; nf++) {
            const int col = base_n + wn + nf * 8 + (lane & 3) * 2;
            const float bv0 = bias[col], bv1 = bias[col + 1];
            acc[mf][nf][0] += bv0; acc[mf][nf][1] += bv1;
            acc[mf][nf][2] += bv0; acc[mf][nf][3] += bv1;
        }
    }
    __nv_bfloat16* outp = g_logits_bf + (size_t)kcomp * BB * AC;
    const int jcol = bn * 4 + (wid & 3);
#pragma unroll
    for (int mf = 0; mf < 4; mf++) {
        const int row = base_m + wm + mf * 16 + q;
#pragma unroll
        for (int nf = 0; nf < 4; nf++) {
            const int col = base_n + wn + nf * 8 + (lane & 3) * 2;
            __nv_bfloat162 p0, p1;
            p0.x = __float2bfloat16(acc[mf][nf][0]);
            p0.y = __float2bfloat16(acc[mf][nf][1]);
            p1.x = __float2bfloat16(acc[mf][nf][2]);
            p1.y = __float2bfloat16(acc[mf][nf][3]);
            *(__nv_bfloat162*)(outp + (size_t)row * AC + col) = p0;
            *(__nv_bfloat162*)(outp + (size_t)(row + 8) * AC + col) = p1;
        }
        float mA = -1e30f, mB = -1e30f;
#pragma unroll
        for (int nf = 0; nf < 4; nf++) {
            mA = fmaxf(mA, fmaxf(acc[mf][nf][0], acc[mf][nf][1]));
            mB = fmaxf(mB, fmaxf(acc[mf][nf][2], acc[mf][nf][3]));
        }
        float sA = 0.f, sB = 0.f;
#pragma unroll
        for (int nf = 0; nf < 4; nf++) {
            sA += __expf(acc[mf][nf][0] - mA) + __expf(acc[mf][nf][1] - mA);
            sB += __expf(acc[mf][nf][2] - mB) + __expf(acc[mf][nf][3] - mB);
        }
#pragma unroll
        for (int o = 1; o <= 2; o <<= 1) {
            float m2 = __shfl_xor_sync(0xFFFFFFFFu, mA, o);
            float s2 = __shfl_xor_sync(0xFFFFFFFFu, sA, o);
            float nm = fmaxf(mA, m2);
            sA = sA * __expf(mA - nm) + s2 * __expf(m2 - nm);
            mA = nm;
            m2 = __shfl_xor_sync(0xFFFFFFFFu, mB, o);
            s2 = __shfl_xor_sync(0xFFFFFFFFu, sB, o);
            nm = fmaxf(mB, m2);
            sB = sB * __expf(mB - nm) + s2 * __expf(m2 - nm);
            mB = nm;
        }
        if ((lane & 3) == 0) {
            const size_t base = ((size_t)kcomp * 32 + jcol) * BB;
            g_pmax[base + row]     = mA;
            g_psum[base + row]     = sA;
            g_pmax[base + row + 8] = mB;
            g_psum[base + row + 8] = sB;
        }
    }
}

// ---------------- merged lse + exact alp: warp per (k,b) --------------------
__global__ void __launch_bounds__(256) lse_alp_kernel(const float* __restrict__ b2_all) {
    const int wid = threadIdx.x >> 5, lane = threadIdx.x & 31;
    const int r = blockIdx.x * 8 + wid;            // r = k*BB + b
    const int k = r >> 13, b = r & (BB - 1);

    // lse from 32 partials (lane j owns partial j)
    float pm = g_pmax[((size_t)k * 32 + lane) * BB + b];
    float ps = g_psum[((size_t)k * 32 + lane) * BB + b];
    float mx = pm;
#pragma unroll
    for (int o = 16; o; o >>= 1) mx = fmaxf(mx, __shfl_xor_sync(0xFFFFFFFFu, mx, o));
    float s = ps * __expf(pm - mx);
#pragma unroll
    for (int o = 16; o; o >>= 1) s += __shfl_xor_sync(0xFFFFFFFFu, s, o);
    const float lse = mx + logf(s);

    // exact alp: fp32 dot of h (fp16, 512) with W2 column (fp32)
    const int a = g_act[b];
    const __half* hrow = g_h_h + ((size_t)k * BB + b) * HID;
    const float* wrow = g_W2t_f + ((size_t)k * AC + a) * HID;
    float d = 0.f;
#pragma unroll
    for (int i = 0; i < 2; i++) {
        const int base = (lane + i * 32) * 8;      // 8 halves per chunk
        const uint4 hv = *(const uint4*)(hrow + base);
        const float4 w0 = *(const float4*)(wrow + base);
        const float4 w1 = *(const float4*)(wrow + base + 4);
        const __half2 h0 = *(const __half2*)&hv.x;
        const __half2 h1 = *(const __half2*)&hv.y;
        const __half2 h2 = *(const __half2*)&hv.z;
        const __half2 h3 = *(const __half2*)&hv.w;
        d += __half2float(h0.x) * w0.x + __half2float(h0.y) * w0.y
           + __half2float(h1.x) * w0.z + __half2float(h1.y) * w0.w
           + __half2float(h2.x) * w1.x + __half2float(h2.y) * w1.y
           + __half2float(h3.x) * w1.z + __half2float(h3.y) * w1.w;
    }
#pragma unroll
    for (int o = 16; o; o >>= 1) d += __shfl_xor_sync(0xFFFFFFFFu, d, o);

    if (lane == 0) {
        g_lse[r] = lse;
        g_alp[r] = d + b2_all[k * AC + a] - lse;
    }
}

// ---------------- per-sequence mixture recursion ----------------------------
__global__ void mix_kernel(const float* __restrict__ prior_all, float* __restrict__ out) {
    const int s = blockIdx.x;
    const int lane = threadIdx.x;
    __shared__ float sm_alp[TT * KC];

    for (int i = lane; i < TT * KC; i += 32) {
        const int t = i >> 3, k = i & 7;
        sm_alp[i] = g_alp[k * BB + s * TT + t];
    }
    __syncthreads();

    if (lane < 8) {
        const int k = lane;
        const float prior = prior_all[s * KC + k];
        float cum = 0.f;
        for (int t = 0; t < TT; t++) {
            const float m = prior + cum;
            float mx = m;
#pragma unroll
            for (int o = 4; o; o >>= 1) mx = fmaxf(mx, __shfl_xor_sync(0xFFu, mx, o));
            float se = expf(m - mx);
#pragma unroll
            for (int o = 4; o; o >>= 1) se += __shfl_xor_sync(0xFFu, se, o);
            g_mix[k * BB + s * TT + t] = m - (mx + logf(se));
            cum += sm_alp[t * 8 + k];
        }
        const float m = prior + cum;
        float mx = m;
#pragma unroll
        for (int o = 4; o; o >>= 1) mx = fmaxf(mx, __shfl_xor_sync(0xFFu, mx, o));
        float se = expf(m - mx);
#pragma unroll
        for (int o = 4; o; o >>= 1) se += __shfl_xor_sync(0xFFu, se, o);
        out[(size_t)BB * AC + s * KC + k] = m - (mx + logf(se));
    }
}

// ---------------- final combine: logsumexp over K (bf16 logits) -------------
__global__ void __launch_bounds__(256) combine_kernel(float* __restrict__ out) {
    const int b = blockIdx.x;
    __shared__ float off[KC];
    if (threadIdx.x < KC) {
        const int k = threadIdx.x;
        off[k] = g_mix[k * BB + b] - g_lse[k * BB + b];
    }
    __syncthreads();

    float o[KC];
#pragma unroll
    for (int k = 0; k < KC; k++) o[k] = off[k];

#pragma unroll
    for (int i = 0; i < 2; i++) {
        const int a2 = threadIdx.x + i * 256;       // bf16x2 pair index 0..511
        float2 v[KC];
#pragma unroll
        for (int k = 0; k < KC; k++) {
            const __nv_bfloat162 p = *(const __nv_bfloat162*)
                (g_logits_bf + ((size_t)k * BB + b) * AC + a2 * 2);
            v[k].x = __bfloat162float(p.x) + o[k];
            v[k].y = __bfloat162float(p.y) + o[k];
        }
        float mx0 = v[0].x, mx1 = v[0].y;
#pragma unroll
        for (int k = 1; k < KC; k++) {
            mx0 = fmaxf(mx0, v[k].x);
            mx1 = fmaxf(mx1, v[k].y);
        }
        float s0 = 0.f, s1 = 0.f;
#pragma unroll
        for (int k = 0; k < KC; k++) {
            s0 += __expf(v[k].x - mx0);
            s1 += __expf(v[k].y - mx1);
        }
        *(float2*)(out + (size_t)b * AC + a2 * 2) =
            make_float2(mx0 + logf(s0), mx1 + logf(s1));
    }
}

// ---------------- launcher ---------------------------------------------------
extern "C" void kernel_launch(void* const* d_in, const int* in_sizes, int n_in,
                              void* d_out, int out_size) {
    const float* obs     = (const float*)d_in[0];
    const void*  actions = d_in[1];
    const float* prior   = (const float*)d_in[2];
    const float* W1      = (const float*)d_in[3];
    const float* b1      = (const float*)d_in[4];
    const float* W2      = (const float*)d_in[5];
    const float* b2      = (const float*)d_in[6];
    float* out = (float*)d_out;

    cudaFuncSetAttribute(gemm1_h,
                         cudaFuncAttributeMaxDynamicSharedMemorySize, SMEM_BYTES);
    cudaFuncSetAttribute(gemm2_h,
                         cudaFuncAttributeMaxDynamicSharedMemorySize, SMEM_BYTES);

    convert_obs_kernel<<<(BB * DIM + 255) / 256, 256>>>(obs);
    transpose_w1_kernel<<<dim3(HID / 32, DIM / 32, KC), dim3(32, 8)>>>(W1);
    transpose_w2_kernel<<<dim3(AC / 32, DIM / 32, KC), dim3(32, 8)>>>(W2);
    prep_actions_kernel<<<1, 1024>>>(actions);

    gemm1_h<<<dim3(HID / 128, BB / 128, KC), 256, SMEM_BYTES>>>(b1);
    gemm2_h<<<dim3(AC / 128, BB / 128, KC), 256, SMEM_BYTES>>>(b2);

    lse_alp_kernel<<<KC * BB / 8, 256>>>(b2);
    mix_kernel<<<SQ, 32>>>(prior, out);
    combine_kernel<<<BB, 256>>>(out);
}